// round 6
// baseline (speedup 1.0000x reference)
#include <cuda_runtime.h>
#include <math.h>

#define NCH 22
#define NS 1125
#define O1 24
#define F2 9
#define KT_ 75
#define TTOT 1050
#define T_CHUNK 20
#define NCHUNK 53
#define NT 256

// packed parameter block offsets (floats)
#define OFF_A 0
#define OFF_D 528
#define OFF_W2 552
#define OFF_CC1 2352
#define OFF_T3 2568
#define OFF_DAW 2577
#define OFF_CC2 2584
#define OFF_T4 2800
#define OFF_L 2812
#define OFF_T2 3340
#define OFF_W 3868
#define OFF_BS 5083
#define PARAM_N 5128

// shared memory layout (floats)
#define SM_XS 5128
#define SM_MU 7218
#define SM_GV 7698
#define SM_X4 7878
#define SM_XA 18966
#define SMEM_FLOATS 23124
#define SMEM_BYTES (SMEM_FLOATS * 4)

__device__ float g_params[PARAM_N];
__device__ float g_feat[256 * 1890];

__device__ __forceinline__ float gelu_f(float v) {
    return 0.5f * v * (1.0f + erff(v * 0.7071067811865476f));
}

// ======================= setup: fold params, build L / T2 ==================
__global__ void lmda_setup(
    const float* __restrict__ cw, const float* __restrict__ t1w,
    const float* __restrict__ bn1, const float* __restrict__ t2w,
    const float* __restrict__ bn2, const float* __restrict__ daw,
    const float* __restrict__ cc1, const float* __restrict__ bn3,
    const float* __restrict__ A, const float* __restrict__ Am,
    const float* __restrict__ chW, const float* __restrict__ chb,
    const float* __restrict__ cc2, const float* __restrict__ bn4)
{
    __shared__ float s1[24], t1[24], s2[24], t2[24], Sw[24];
    __shared__ float s3[9], t3[9], s4[9], t4[9];
    __shared__ float Ap[484], dis[22], Lh[484];
    int tid = threadIdx.x;

    if (tid < 24) {
        float s = bn1[tid] / sqrtf(bn1[72 + tid] + 1e-5f);
        s1[tid] = s; t1[tid] = bn1[24 + tid] - bn1[48 + tid] * s;
        s = bn2[tid] / sqrtf(bn2[72 + tid] + 1e-5f);
        s2[tid] = s; t2[tid] = bn2[24 + tid] - bn2[48 + tid] * s;
        float ss = 0.f;
        for (int k = 0; k < KT_; k++) ss += t2w[tid * KT_ + k];
        Sw[tid] = ss;
    }
    if (tid < 9) {
        float s = bn3[tid] / sqrtf(bn3[27 + tid] + 1e-5f);
        s3[tid] = s; t3[tid] = bn3[9 + tid] - bn3[18 + tid] * s;
        s = bn4[tid] / sqrtf(bn4[27 + tid] + 1e-5f);
        s4[tid] = s; t4[tid] = bn4[9 + tid] - bn4[18 + tid] * s;
    }
    __syncthreads();

    for (int i = tid; i < 528; i += NT) {
        int o = i / 22, c = i % 22;
        float m = 0.f;
        for (int j = 0; j < 9; j++) m += t1w[o * 9 + j] * cw[j * 22 + c];
        g_params[OFF_A + i] = s2[o] * s1[o] * m;
    }
    if (tid < 24) g_params[OFF_D + tid] = s2[tid] * t1[tid] * Sw[tid] + t2[tid];
    for (int i = tid; i < 1800; i += NT) {
        int k = i / 24, o = i % 24;
        g_params[OFF_W2 + i] = t2w[o * KT_ + k];
    }
    for (int i = tid; i < 216; i += NT) {
        int f = i / 24, o = i % 24;
        g_params[OFF_CC1 + i] = 22.0f * s3[f] * cc1[f * 24 + o];
    }
    if (tid < 9) g_params[OFF_T3 + tid] = t3[tid];
    if (tid < 7) g_params[OFF_DAW + tid] = daw[tid];
    for (int i = tid; i < 216; i += NT) {
        int f = i / 24, c = i % 24;
        g_params[OFF_CC2 + i] = (c < 22) ? s4[f] * cc2[f * 22 + c] : 0.f;
    }
    if (tid < 9) g_params[OFF_T4 + tid] = t4[tid];

    for (int i = tid; i < 484; i += NT) {
        int c = i / 22, d = i % 22;
        float v = fmaxf(A[i] / (1.0f + expf(-Am[i])), 0.0f);
        Ap[i] = (c == d) ? 0.f : v;
    }
    __syncthreads();
    if (tid < 22) {
        float r = 0.f;
        for (int d = 0; d < 22; d++) r += Ap[tid * 22 + d] + Ap[d * 22 + tid];
        dis[tid] = 1.0f / sqrtf(r + 1e-10f);
    }
    __syncthreads();
    for (int i = tid; i < 484; i += NT) {
        int c = i / 22, d = i % 22;
        Lh[i] = -dis[c] * (Ap[c * 22 + d] + Ap[d * 22 + c]) * dis[d];
    }
    __syncthreads();
    for (int i = tid; i < 528; i += NT) {
        int d = i / 24, c = i % 24;
        g_params[OFF_L + i] = (c < 22) ? Lh[d * 22 + c] : 0.f;
        float v = 0.f;
        if (c < 22) {
            for (int e = 0; e < 22; e++) v += Lh[d * 22 + e] * Lh[e * 22 + c];
            v = 2.0f * v - ((c == d) ? 1.0f : 0.0f);
        }
        g_params[OFF_T2 + i] = v;
    }
    for (int i = tid; i < 1215; i += NT) g_params[OFF_W + i] = chW[i];
    for (int i = tid; i < 45; i += NT) {
        int l = i / 9, o = i % 9;
        g_params[OFF_BS + i] = chb[l * 27 + o] + chb[l * 27 + 9 + o] + chb[l * 27 + 18 + o];
    }
}

// ======================= main fused kernel ==================================
__global__ void __launch_bounds__(NT, 2) lmda_main(const float* __restrict__ x)
{
    extern __shared__ float sm[];
    const int tid = threadIdx.x;
    const int t0 = blockIdx.x * T_CHUNK;
    const int b = blockIdx.y;
    const int Tc = min(T_CHUNK, TTOT - t0);   // 20 or 10 (multiple of 5, even)

    for (int i = tid; i < PARAM_N; i += NT) sm[i] = g_params[i];
    {
        const int W = Tc + 74;
        const float* xb = x + (size_t)b * NCH * NS + t0;
        for (int i = tid; i < NCH * W; i += NT) {
            int c = i / W, j = i % W;
            sm[SM_XS + c * 95 + j] = xb[c * NS + j];
        }
    }
    __syncthreads();

    // B: 75-tap conv (24 filters) + affine + gelu -> x4[o][c][t] (stride 21)
    {
        const int npair = Tc >> 1;
        for (int it = tid; it < 22 * npair; it += NT) {
            int tp = it / 22, c = it % 22, t1 = tp * 2;
            float a0[O1], a1[O1];
            #pragma unroll
            for (int o = 0; o < O1; o++) { a0[o] = 0.f; a1[o] = 0.f; }
            const float* xr = &sm[SM_XS + c * 95 + t1];
            for (int k = 0; k < KT_; k++) {
                float x0 = xr[k], x1 = xr[k + 1];
                const float4* w4 = (const float4*)&sm[OFF_W2 + k * 24];
                #pragma unroll
                for (int q = 0; q < 6; q++) {
                    float4 w = w4[q];
                    a0[4*q+0] = fmaf(x0, w.x, a0[4*q+0]); a1[4*q+0] = fmaf(x1, w.x, a1[4*q+0]);
                    a0[4*q+1] = fmaf(x0, w.y, a0[4*q+1]); a1[4*q+1] = fmaf(x1, w.y, a1[4*q+1]);
                    a0[4*q+2] = fmaf(x0, w.z, a0[4*q+2]); a1[4*q+2] = fmaf(x1, w.z, a1[4*q+2]);
                    a0[4*q+3] = fmaf(x0, w.w, a0[4*q+3]); a1[4*q+3] = fmaf(x1, w.w, a1[4*q+3]);
                }
            }
            #pragma unroll
            for (int o = 0; o < O1; o++) {
                float av = sm[OFF_A + o * 22 + c], dv = sm[OFF_D + o];
                float* dst = &sm[SM_X4 + (o * 22 + c) * 21 + t1];
                dst[0] = gelu_f(fmaf(av, a0[o], dv));
                dst[1] = gelu_f(fmaf(av, a1[o], dv));
            }
        }
    }
    __syncthreads();

    // C1: mean over channels
    for (int it = tid; it < O1 * Tc; it += NT) {
        int o = it / Tc, t = it % Tc;
        const float* xr = &sm[SM_X4 + o * 22 * 21 + t];
        float s = 0.f;
        #pragma unroll
        for (int c = 0; c < 22; c++) s += xr[c * 21];
        sm[SM_MU + o * T_CHUNK + t] = s * (1.0f / 22.0f);
    }
    __syncthreads();

    // C2: depth conv(7) + softmax over depth (da_b cancels in softmax)
    if (tid < Tc) {
        float m[O1], y[O1];
        #pragma unroll
        for (int o = 0; o < O1; o++) m[o] = sm[SM_MU + o * T_CHUNK + tid];
        #pragma unroll
        for (int o = 0; o < O1; o++) {
            float s = 0.f;
            #pragma unroll
            for (int j = 0; j < 7; j++) {
                int oo = o - 3 + j;
                if (oo >= 0 && oo < O1) s = fmaf(sm[OFF_DAW + j], m[oo], s);
            }
            y[o] = s;
        }
        float mx = -1e30f;
        #pragma unroll
        for (int o = 0; o < O1; o++) mx = fmaxf(mx, y[o]);
        float sum = 0.f;
        #pragma unroll
        for (int o = 0; o < O1; o++) { y[o] = expf(y[o] - mx); sum += y[o]; }
        float inv = 1.0f / sum;
        #pragma unroll
        for (int o = 0; o < O1; o++) sm[SM_MU + o * T_CHUNK + tid] = y[o] * inv;
    }
    __syncthreads();

    // D: attention * cconv1 + BN3 -> Xa[f][c][t]
    for (int it = tid; it < F2 * Tc; it += NT) {
        int f = it / Tc, t = it % Tc;
        float acc[22];
        #pragma unroll
        for (int c = 0; c < 22; c++) acc[c] = 0.f;
        #pragma unroll
        for (int o = 0; o < O1; o++) {
            float coef = sm[OFF_CC1 + f * 24 + o] * sm[SM_MU + o * T_CHUNK + t];
            const float* xr = &sm[SM_X4 + o * 22 * 21 + t];
            #pragma unroll
            for (int c = 0; c < 22; c++) acc[c] = fmaf(coef, xr[c * 21], acc[c]);
        }
        float tb = sm[OFF_T3 + f];
        #pragma unroll
        for (int c = 0; c < 22; c++) sm[SM_XA + (f * 22 + c) * 21 + t] = acc[c] + tb;
    }
    __syncthreads();

    // Chebyshev: 5 layers, adjs = {I, L, 2L^2-I}, ping-pong XA <-> X4
    for (int l = 0; l < 5; l++) {
        const float* Xc = (l & 1) ? &sm[SM_X4] : &sm[SM_XA];
        float*       Xn = (l & 1) ? &sm[SM_XA] : &sm[SM_X4];
        const float* Wl = &sm[OFF_W + l * 243];
        for (int it = tid; it < F2 * Tc; it += NT) {
            int o = it / Tc, t = it % Tc;
            float out[24], z1[22], z2[22];
            #pragma unroll
            for (int i = 0; i < 24; i++) out[i] = 0.f;
            #pragma unroll
            for (int i = 0; i < 22; i++) { z1[i] = 0.f; z2[i] = 0.f; }
            #pragma unroll
            for (int f = 0; f < 9; f++) {
                float w0 = Wl[f * 9 + o], w1 = Wl[81 + f * 9 + o], w2 = Wl[162 + f * 9 + o];
                const float* xr = &Xc[f * 22 * 21 + t];
                #pragma unroll
                for (int d = 0; d < 22; d++) {
                    float xv = xr[d * 21];
                    out[d] = fmaf(w0, xv, out[d]);
                    z1[d]  = fmaf(w1, xv, z1[d]);
                    z2[d]  = fmaf(w2, xv, z2[d]);
                }
            }
            #pragma unroll
            for (int d = 0; d < 22; d++) {
                float v1 = z1[d], v2 = z2[d];
                const float4* Lr = (const float4*)&sm[OFF_L + d * 24];
                const float4* Tr = (const float4*)&sm[OFF_T2 + d * 24];
                #pragma unroll
                for (int q = 0; q < 6; q++) {
                    float4 lv = Lr[q], tv = Tr[q];
                    out[4*q+0] = fmaf(v1, lv.x, fmaf(v2, tv.x, out[4*q+0]));
                    out[4*q+1] = fmaf(v1, lv.y, fmaf(v2, tv.y, out[4*q+1]));
                    out[4*q+2] = fmaf(v1, lv.z, fmaf(v2, tv.z, out[4*q+2]));
                    out[4*q+3] = fmaf(v1, lv.w, fmaf(v2, tv.w, out[4*q+3]));
                }
            }
            float bs = sm[OFF_BS + l * 9 + o];
            #pragma unroll
            for (int d = 0; d < 22; d++)
                Xn[(o * 22 + d) * 21 + t] = fmaxf(out[d] + bs, 0.f);
        }
        __syncthreads();
    }

    // E: cconv2 (+BN4 folded) + gelu -> gv[f][t]   (result of layer 4 is in SM_X4)
    for (int it = tid; it < F2 * Tc; it += NT) {
        int f = it / Tc, t = it % Tc;
        const float* xr = &sm[SM_X4 + f * 22 * 21 + t];
        float v = sm[OFF_T4 + f];
        #pragma unroll
        for (int c = 0; c < 22; c++) v = fmaf(sm[OFF_CC2 + f * 24 + c], xr[c * 21], v);
        sm[SM_GV + f * T_CHUNK + t] = gelu_f(v);
    }
    __syncthreads();

    // F: avgpool5 -> features
    {
        int np = Tc / 5;
        for (int it = tid; it < F2 * np; it += NT) {
            int f = it / np, p = it % np;
            const float* g = &sm[SM_GV + f * T_CHUNK + p * 5];
            float s = (g[0] + g[1] + g[2] + g[3] + g[4]) * 0.2f;
            g_feat[b * 1890 + f * 210 + t0 / 5 + p] = s;
        }
    }
}

// ======================= fc + mlp + softmax =================================
__global__ void lmda_fc(const float* __restrict__ fc1w, const float* __restrict__ fc1b,
                        const float* __restrict__ w1, const float* __restrict__ b1,
                        const float* __restrict__ w2, const float* __restrict__ b2,
                        float* __restrict__ out)
{
    __shared__ float part[NT * 5];
    __shared__ float h64s[64];
    int b = blockIdx.x, tid = threadIdx.x;
    float p[5] = {0, 0, 0, 0, 0};
    const float* fr = &g_feat[b * 1890];
    for (int i = tid; i < 1890; i += NT) {
        float fv = fr[i];
        const float* w = &fc1w[i * 5];
        #pragma unroll
        for (int j = 0; j < 5; j++) p[j] = fmaf(fv, w[j], p[j]);
    }
    #pragma unroll
    for (int j = 0; j < 5; j++) part[tid * 5 + j] = p[j];
    __syncthreads();
    for (int s = NT / 2; s > 0; s >>= 1) {
        if (tid < s)
            #pragma unroll
            for (int j = 0; j < 5; j++) part[tid * 5 + j] += part[(tid + s) * 5 + j];
        __syncthreads();
    }
    if (tid < 64) {
        float h5[5];
        #pragma unroll
        for (int j = 0; j < 5; j++) h5[j] = part[j] + fc1b[j];
        float s = b1[tid];
        #pragma unroll
        for (int i = 0; i < 5; i++) s = fmaf(h5[i], w1[i * 64 + tid], s);
        h64s[tid] = (s > 0.f) ? s : expm1f(s);   // elu
    }
    __syncthreads();
    if (tid == 0) {
        float o4[4];
        #pragma unroll
        for (int j = 0; j < 4; j++) o4[j] = b2[j];
        for (int i = 0; i < 64; i++) {
            float h = h64s[i];
            #pragma unroll
            for (int j = 0; j < 4; j++) o4[j] = fmaf(h, w2[i * 4 + j], o4[j]);
        }
        float mx = fmaxf(fmaxf(o4[0], o4[1]), fmaxf(o4[2], o4[3]));
        float sum = 0.f;
        #pragma unroll
        for (int j = 0; j < 4; j++) { o4[j] = expf(o4[j] - mx); sum += o4[j]; }
        float inv = 1.0f / sum;
        #pragma unroll
        for (int j = 0; j < 4; j++) out[b * 4 + j] = o4[j] * inv;
    }
}

// ======================= launch =============================================
extern "C" void kernel_launch(void* const* d_in, const int* in_sizes, int n_in,
                              void* d_out, int out_size)
{
    const float* x    = (const float*)d_in[0];
    const float* cw   = (const float*)d_in[1];
    const float* t1w  = (const float*)d_in[2];
    const float* bn1  = (const float*)d_in[3];
    const float* t2w  = (const float*)d_in[4];
    const float* bn2  = (const float*)d_in[5];
    const float* daw  = (const float*)d_in[6];
    // d_in[7] = da_b (cancels in softmax)
    const float* cc1  = (const float*)d_in[8];
    const float* bn3  = (const float*)d_in[9];
    const float* A    = (const float*)d_in[10];
    const float* Am   = (const float*)d_in[11];
    const float* chW  = (const float*)d_in[12];
    const float* chb  = (const float*)d_in[13];
    const float* cc2  = (const float*)d_in[14];
    const float* bn4  = (const float*)d_in[15];
    const float* fc1w = (const float*)d_in[16];
    const float* fc1b = (const float*)d_in[17];
    const float* w1   = (const float*)d_in[18];
    const float* b1   = (const float*)d_in[19];
    const float* w2   = (const float*)d_in[20];
    const float* b2   = (const float*)d_in[21];

    static int smem_set = 0;
    if (!smem_set) {
        cudaFuncSetAttribute(lmda_main, cudaFuncAttributeMaxDynamicSharedMemorySize,
                             SMEM_BYTES);
        smem_set = 1;
    }

    lmda_setup<<<1, NT>>>(cw, t1w, bn1, t2w, bn2, daw, cc1, bn3, A, Am,
                          chW, chb, cc2, bn4);
    lmda_main<<<dim3(NCHUNK, 256), NT, SMEM_BYTES>>>(x);
    lmda_fc<<<256, NT>>>(fc1w, fc1b, w1, b1, w2, b2, (float*)d_out);
}